// round 14
// baseline (speedup 1.0000x reference)
#include <cuda_runtime.h>
#include <cstdint>

#define NN 16
#define CC 64
#define OO 64
#define HH 128
#define WW 128
#define KH 16
#define KW 16
#define HO 113
#define WO 113
#define TH 4        // h rows per CTA; grid (29,16) = 464 CTAs
#define RW 144      // staged row width (floats)
#define ROWS_WORDS (19 * RW)

// ---------------- scratch globals ----------------
__device__ float g_ny [OO*CC*KH*KW];     // normalized y
__device__ float g_S  [NN*HH*WW];
__device__ float g_T  [NN*HH*WW];
__device__ float g_inv[NN*HO*WO];
__device__ uint2 g_bf [CC*KH*8*32];      // fp16 B frags: [c][kh][n8(8)][lane(32)] = 2MB

// ---------------- helpers ----------------
__device__ __forceinline__ uint32_t smem_u32(const void* p) {
    uint32_t a;
    asm("{ .reg .u64 t; cvta.to.shared.u64 t, %1; cvt.u32.u64 %0, t; }"
        : "=r"(a) : "l"(p));
    return a;
}
__device__ __forceinline__ void cpa16(uint32_t dst, const void* src) {
    asm volatile("cp.async.cg.shared.global [%0], [%1], 16;"
                 :: "r"(dst), "l"(src) : "memory");
}
__device__ __forceinline__ uint32_t pack_h2(float hi, float lo) {
    uint32_t r;
    asm("cvt.rn.f16x2.f32 %0, %1, %2;" : "=r"(r) : "f"(hi), "f"(lo));
    return r;
}
__device__ __forceinline__ void mma_f16(float* c, uint32_t a0, uint32_t a1,
                                        uint32_t a2, uint32_t a3,
                                        uint32_t b0, uint32_t b1) {
    asm volatile(
        "mma.sync.aligned.m16n8k16.row.col.f32.f16.f16.f32 "
        "{%0,%1,%2,%3}, {%4,%5,%6,%7}, {%8,%9}, {%0,%1,%2,%3};"
        : "+f"(c[0]), "+f"(c[1]), "+f"(c[2]), "+f"(c[3])
        : "r"(a0), "r"(a1), "r"(a2), "r"(a3), "r"(b0), "r"(b1));
}

// ---------------- prep: normalize y ----------------
__global__ void k_norm_y(const float* __restrict__ y) {
    int o = blockIdx.x, tid = threadIdx.x;
    const float* yo = y + o * (CC*KH*KW);
    float s = 0.f;
    for (int i = tid; i < CC*KH*KW; i += 256) { float v = yo[i]; s += v * v; }
    __shared__ float red[256];
    red[tid] = s; __syncthreads();
    for (int st = 128; st > 0; st >>= 1) {
        if (tid < st) red[tid] += red[tid + st];
        __syncthreads();
    }
    float rinv = rsqrtf(red[0]);
    for (int i = tid; i < CC*KH*KW; i += 256)
        g_ny[o * (CC*KH*KW) + i] = yo[i] * rinv;
}

// ---------------- prep: precompute fp16 B fragments (m16n8k16) ----------------
__global__ void k_bfrag() {
    int ch = blockIdx.x;
    int kh = ch & 15, c = ch >> 4;
    int n8 = threadIdx.x >> 5, lane = threadIdx.x & 31;
    int gid = lane >> 2, tig = lane & 3;
    int o = n8 * 8 + gid;
    const float* yb = g_ny + o * (CC*KH*KW) + c * (KH*KW) + kh * KW;
    int k0 = 2 * tig;
    uint2 r;
    r.x = pack_h2(yb[k0 + 1], yb[k0]);
    r.y = pack_h2(yb[k0 + 9], yb[k0 + 8]);
    g_bf[(ch * 8 + n8) * 32 + lane] = r;
}

// ---------------- prep: x-norm pipeline ----------------
__global__ void k_xsq(const float* __restrict__ x) {
    int idx = blockIdx.x * 256 + threadIdx.x;
    int n = idx >> 14, p = idx & 16383;
    const float* xp = x + n * (CC*HH*WW) + p;
    float s = 0.f;
    #pragma unroll 8
    for (int c = 0; c < CC; c++) { float v = xp[c * (HH*WW)]; s += v * v; }
    g_S[idx] = s;
}
__global__ void k_boxw() {
    int b = blockIdx.x;
    __shared__ float row[WW];
    row[threadIdx.x] = g_S[b * WW + threadIdx.x];
    __syncthreads();
    int w = threadIdx.x;
    if (w < WO) {
        float s = 0.f;
        #pragma unroll
        for (int k = 0; k < KW; k++) s += row[w + k];
        g_T[b * WW + w] = s;
    }
}
__global__ void k_boxh() {
    int idx = blockIdx.x * 256 + threadIdx.x;
    if (idx >= NN*HO*WO) return;
    int n = idx / (HO*WO), r = idx % (HO*WO);
    int h = r / WO, w = r % WO;
    float s = 0.f;
    #pragma unroll
    for (int k = 0; k < KH; k++) s += g_T[(n * HH + h + k) * WW + w];
    g_inv[idx] = rsqrtf(s);
}

// ---------------- main conv: fp16 m16n8k16; rows via cp.async, B via LDG ----------------
// grid (29, 16): h-tile (4 rows), n. 512 threads = 16 warps.
// warp: wm = wid&7 -> dh = wm>>1, whalf = wm&1 ; ns = wid>>3 (o half)
// warp tile: 64 m (fixed dh, w in [whalf*64,+64)) x 32 n (o in [ns*32,+32))
__global__ __launch_bounds__(512, 1) void k_conv_mma(const float* __restrict__ x,
                                                     float* __restrict__ out) {
    __shared__ float rows2[2][ROWS_WORDS];
    uint32_t sbase = smem_u32(rows2);

    int tid = threadIdx.x, lane = tid & 31, wid = tid >> 5;
    int n = blockIdx.y, h0 = blockIdx.x * TH;
    int wm = wid & 7, ns = wid >> 3;
    int dh = wm >> 1, whalf = wm & 1;
    int gid = lane >> 2, tig = lane & 3;
    int aoff = whalf * 64 + gid + 2 * tig;

    const float* xn = x + n * (CC*HH*WW);
    // per-warp B pointer: [(c*16+kh)*8 + ns*4 + t]*32 + lane
    const uint2* __restrict__ gB = g_bf + (ns * 4) * 32 + lane;

    // zero the pad region (cols 128..143) of both row buffers
    for (int i = tid; i < 2 * 19 * 16; i += 512) {
        int buf = i / (19 * 16), j = (i / 16) % 19, col = 128 + (i & 15);
        rows2[buf][j * RW + col] = 0.f;
    }

    float acc[4][4][4];
    #pragma unroll
    for (int mt = 0; mt < 4; mt++)
        #pragma unroll
        for (int t = 0; t < 4; t++)
            #pragma unroll
            for (int r = 0; r < 4; r++) acc[mt][t][r] = 0.f;

    // ---- staging (cp.async): 19 rows x 32 float4 ----
    auto stage = [&](int c, int buf) {
        const float* xr = xn + c * (HH*WW);
        uint32_t rb = sbase + buf * (ROWS_WORDS * 4);
        for (int i = tid; i < 19 * 32; i += 512) {
            int j = i >> 5, c4 = i & 31;
            int row = h0 + j; if (row > HH - 1) row = HH - 1;
            cpa16(rb + (j * RW + c4 * 4) * 4, xr + row * WW + c4 * 4);
        }
    };

    stage(0, 0);
    asm volatile("cp.async.commit_group;" ::: "memory");

    for (int c = 0; c < CC; c++) {
        int buf = c & 1;
        if (c + 1 < CC) {
            stage(c + 1, buf ^ 1);
            asm volatile("cp.async.commit_group;" ::: "memory");
            asm volatile("cp.async.wait_group 1;" ::: "memory");
        } else {
            asm volatile("cp.async.wait_group 0;" ::: "memory");
        }
        __syncthreads();           // staged rows visible

        const float* rows = rows2[buf];
        const uint2* __restrict__ gBc = gB + c * (KH * 8 * 32);

        // prefetch B for kh=0
        uint2 bc[4];
        #pragma unroll
        for (int t = 0; t < 4; t++) bc[t] = gBc[t * 32];

        #pragma unroll
        for (int kh = 0; kh < KH; kh++) {
            // prefetch B for kh+1 while computing kh
            uint2 bn[4];
            if (kh + 1 < KH) {
                const uint2* gn = gBc + (kh + 1) * 256;
                #pragma unroll
                for (int t = 0; t < 4; t++) bn[t] = gn[t * 32];
            }
            const float* rbase = rows + (kh + dh) * RW + aoff;
            // Toeplitz A: 9 packed fp16 pairs cover all 4 m-tiles
            uint32_t pk[9];
            #pragma unroll
            for (int j = 0; j < 9; j++)
                pk[j] = pack_h2(rbase[8 * j + 1], rbase[8 * j]);
            #pragma unroll
            for (int t = 0; t < 4; t++) {
                #pragma unroll
                for (int mt = 0; mt < 4; mt++)
                    mma_f16(acc[mt][t], pk[2*mt], pk[2*mt+1],
                            pk[2*mt+1], pk[2*mt+2], bc[t].x, bc[t].y);
            }
            #pragma unroll
            for (int t = 0; t < 4; t++) bc[t] = bn[t];
        }
        __syncthreads();           // all row reads done before next overwrite
    }

    // epilogue: scale by 1/||x_win||, relu, store
    int h = h0 + dh;
    if (h < HO) {
        const float* ivrow = g_inv + (n * HO + h) * WO;
        #pragma unroll
        for (int mt = 0; mt < 4; mt++) {
            int w0 = whalf * 64 + mt * 16 + gid;
            float iv0 = (w0 < WO)     ? ivrow[w0]     : 0.f;
            float iv8 = (w0 + 8 < WO) ? ivrow[w0 + 8] : 0.f;
            #pragma unroll
            for (int t = 0; t < 4; t++) {
                int o = ns * 32 + t * 8 + tig * 2;
                float* ob = out + ((n * OO + o) * HO + h) * WO;
                if (w0 < WO) {
                    float v0 = acc[mt][t][0] * iv0;
                    float v1 = acc[mt][t][1] * iv0;
                    ob[w0]           = v0 > 0.f ? v0 : 0.f;
                    ob[HO*WO + w0]   = v1 > 0.f ? v1 : 0.f;
                }
                if (w0 + 8 < WO) {
                    float v2 = acc[mt][t][2] * iv8;
                    float v3 = acc[mt][t][3] * iv8;
                    ob[w0 + 8]         = v2 > 0.f ? v2 : 0.f;
                    ob[HO*WO + w0 + 8] = v3 > 0.f ? v3 : 0.f;
                }
            }
        }
    }
}

extern "C" void kernel_launch(void* const* d_in, const int* in_sizes, int n_in,
                              void* d_out, int out_size) {
    const float* x = (const float*)d_in[0];   // (16,64,128,128)
    const float* y = (const float*)d_in[1];   // (64,64,16,16)
    float* out = (float*)d_out;               // (16,64,113,113)

    k_norm_y<<<OO, 256>>>(y);
    k_bfrag<<<CC*KH, 256>>>();
    k_xsq<<<(NN*HH*WW) / 256, 256>>>(x);
    k_boxw<<<NN * HH, WW>>>();
    k_boxh<<<(NN*HO*WO + 255) / 256, 256>>>();

    dim3 grid((HO + TH - 1) / TH, NN);
    k_conv_mma<<<grid, 512>>>(x, out);
}

// round 15
// speedup vs baseline: 1.3694x; 1.3694x over previous
#include <cuda_runtime.h>
#include <cstdint>

#define NN 16
#define CC 64
#define OO 64
#define HH 128
#define WW 128
#define KH 16
#define KW 16
#define HO 113
#define WO 113
#define TH 2        // h rows per CTA; grid (57,16) = 912 CTAs, occ 2
#define RW 144      // staged row width (floats)
#define NROWS 17    // TH + KH - 1
#define ROWS_WORDS (NROWS * RW)

// ---------------- scratch globals ----------------
__device__ float g_ny [OO*CC*KH*KW];     // normalized y
__device__ float g_S  [NN*HH*WW];
__device__ float g_T  [NN*HH*WW];
__device__ float g_inv[NN*HO*WO];
__device__ uint2 g_bf [CC*KH*8*32];      // fp16 B frags: [c][kh][n8(8)][lane(32)] = 2MB

// ---------------- helpers ----------------
__device__ __forceinline__ uint32_t smem_u32(const void* p) {
    uint32_t a;
    asm("{ .reg .u64 t; cvta.to.shared.u64 t, %1; cvt.u32.u64 %0, t; }"
        : "=r"(a) : "l"(p));
    return a;
}
__device__ __forceinline__ void cpa16(uint32_t dst, const void* src) {
    asm volatile("cp.async.cg.shared.global [%0], [%1], 16;"
                 :: "r"(dst), "l"(src) : "memory");
}
__device__ __forceinline__ uint32_t pack_h2(float hi, float lo) {
    uint32_t r;
    asm("cvt.rn.f16x2.f32 %0, %1, %2;" : "=r"(r) : "f"(hi), "f"(lo));
    return r;
}
__device__ __forceinline__ void mma_f16(float* c, uint32_t a0, uint32_t a1,
                                        uint32_t a2, uint32_t a3,
                                        uint32_t b0, uint32_t b1) {
    asm volatile(
        "mma.sync.aligned.m16n8k16.row.col.f32.f16.f16.f32 "
        "{%0,%1,%2,%3}, {%4,%5,%6,%7}, {%8,%9}, {%0,%1,%2,%3};"
        : "+f"(c[0]), "+f"(c[1]), "+f"(c[2]), "+f"(c[3])
        : "r"(a0), "r"(a1), "r"(a2), "r"(a3), "r"(b0), "r"(b1));
}

// ---------------- prep: normalize y ----------------
__global__ void k_norm_y(const float* __restrict__ y) {
    int o = blockIdx.x, tid = threadIdx.x;
    const float* yo = y + o * (CC*KH*KW);
    float s = 0.f;
    for (int i = tid; i < CC*KH*KW; i += 256) { float v = yo[i]; s += v * v; }
    __shared__ float red[256];
    red[tid] = s; __syncthreads();
    for (int st = 128; st > 0; st >>= 1) {
        if (tid < st) red[tid] += red[tid + st];
        __syncthreads();
    }
    float rinv = rsqrtf(red[0]);
    for (int i = tid; i < CC*KH*KW; i += 256)
        g_ny[o * (CC*KH*KW) + i] = yo[i] * rinv;
}

// ---------------- prep: precompute fp16 B fragments (m16n8k16) ----------------
__global__ void k_bfrag() {
    int ch = blockIdx.x;
    int kh = ch & 15, c = ch >> 4;
    int n8 = threadIdx.x >> 5, lane = threadIdx.x & 31;
    int gid = lane >> 2, tig = lane & 3;
    int o = n8 * 8 + gid;
    const float* yb = g_ny + o * (CC*KH*KW) + c * (KH*KW) + kh * KW;
    int k0 = 2 * tig;
    uint2 r;
    r.x = pack_h2(yb[k0 + 1], yb[k0]);
    r.y = pack_h2(yb[k0 + 9], yb[k0 + 8]);
    g_bf[(ch * 8 + n8) * 32 + lane] = r;
}

// ---------------- prep: x-norm pipeline ----------------
__global__ void k_xsq(const float* __restrict__ x) {
    int idx = blockIdx.x * 256 + threadIdx.x;
    int n = idx >> 14, p = idx & 16383;
    const float* xp = x + n * (CC*HH*WW) + p;
    float s = 0.f;
    #pragma unroll 8
    for (int c = 0; c < CC; c++) { float v = xp[c * (HH*WW)]; s += v * v; }
    g_S[idx] = s;
}
__global__ void k_boxw() {
    int b = blockIdx.x;
    __shared__ float row[WW];
    row[threadIdx.x] = g_S[b * WW + threadIdx.x];
    __syncthreads();
    int w = threadIdx.x;
    if (w < WO) {
        float s = 0.f;
        #pragma unroll
        for (int k = 0; k < KW; k++) s += row[w + k];
        g_T[b * WW + w] = s;
    }
}
__global__ void k_boxh() {
    int idx = blockIdx.x * 256 + threadIdx.x;
    if (idx >= NN*HO*WO) return;
    int n = idx / (HO*WO), r = idx % (HO*WO);
    int h = r / WO, w = r % WO;
    float s = 0.f;
    #pragma unroll
    for (int k = 0; k < KH; k++) s += g_T[(n * HH + h + k) * WW + w];
    g_inv[idx] = rsqrtf(s);
}

// ---------------- main conv: fp16 m16n8k16, occupancy 2 ----------------
// grid (57, 16): h-tile (2 rows), n. 256 threads = 8 warps, 2 CTAs/SM.
// warp: wm = wid&3 -> dh = wm>>1, whalf = wm&1 ; ns = wid>>2 (o half)
// warp tile: 64 m (fixed dh, w in [whalf*64,+64)) x 32 n (o in [ns*32,+32))
__global__ __launch_bounds__(256, 2) void k_conv_mma(const float* __restrict__ x,
                                                     float* __restrict__ out) {
    __shared__ float rows2[2][ROWS_WORDS];
    uint32_t sbase = smem_u32(rows2);

    int tid = threadIdx.x, lane = tid & 31, wid = tid >> 5;
    int n = blockIdx.y, h0 = blockIdx.x * TH;
    int wm = wid & 3, ns = wid >> 2;
    int dh = wm >> 1, whalf = wm & 1;
    int gid = lane >> 2, tig = lane & 3;
    int aoff = whalf * 64 + gid + 2 * tig;

    const float* xn = x + n * (CC*HH*WW);
    // per-warp B pointer: [(c*16+kh)*8 + ns*4 + t]*32 + lane
    const uint2* __restrict__ gB = g_bf + (ns * 4) * 32 + lane;

    // zero the pad region (cols 128..143) of both row buffers
    for (int i = tid; i < 2 * NROWS * 16; i += 256) {
        int buf = i / (NROWS * 16), j = (i / 16) % NROWS, col = 128 + (i & 15);
        rows2[buf][j * RW + col] = 0.f;
    }

    float acc[4][4][4];
    #pragma unroll
    for (int mt = 0; mt < 4; mt++)
        #pragma unroll
        for (int t = 0; t < 4; t++)
            #pragma unroll
            for (int r = 0; r < 4; r++) acc[mt][t][r] = 0.f;

    // ---- staging (cp.async): NROWS x 32 float4 ----
    auto stage = [&](int c, int buf) {
        const float* xr = xn + c * (HH*WW);
        uint32_t rb = sbase + buf * (ROWS_WORDS * 4);
        for (int i = tid; i < NROWS * 32; i += 256) {
            int j = i >> 5, c4 = i & 31;
            int row = h0 + j; if (row > HH - 1) row = HH - 1;
            cpa16(rb + (j * RW + c4 * 4) * 4, xr + row * WW + c4 * 4);
        }
    };

    stage(0, 0);
    asm volatile("cp.async.commit_group;" ::: "memory");

    for (int c = 0; c < CC; c++) {
        int buf = c & 1;
        if (c + 1 < CC) {
            stage(c + 1, buf ^ 1);
            asm volatile("cp.async.commit_group;" ::: "memory");
            asm volatile("cp.async.wait_group 1;" ::: "memory");
        } else {
            asm volatile("cp.async.wait_group 0;" ::: "memory");
        }
        __syncthreads();           // staged rows visible

        const float* rows = rows2[buf];
        const uint2* __restrict__ gBc = gB + c * (KH * 8 * 32);

        // prefetch B for kh=0
        uint2 bc[4];
        #pragma unroll
        for (int t = 0; t < 4; t++) bc[t] = gBc[t * 32];

        #pragma unroll
        for (int kh = 0; kh < KH; kh++) {
            // prefetch B for kh+1 while computing kh
            uint2 bn[4];
            if (kh + 1 < KH) {
                const uint2* gn = gBc + (kh + 1) * 256;
                #pragma unroll
                for (int t = 0; t < 4; t++) bn[t] = gn[t * 32];
            }
            const float* rbase = rows + (kh + dh) * RW + aoff;
            // Toeplitz A: 9 packed fp16 pairs cover all 4 m-tiles
            uint32_t pk[9];
            #pragma unroll
            for (int j = 0; j < 9; j++)
                pk[j] = pack_h2(rbase[8 * j + 1], rbase[8 * j]);
            #pragma unroll
            for (int t = 0; t < 4; t++) {
                #pragma unroll
                for (int mt = 0; mt < 4; mt++)
                    mma_f16(acc[mt][t], pk[2*mt], pk[2*mt+1],
                            pk[2*mt+1], pk[2*mt+2], bc[t].x, bc[t].y);
            }
            #pragma unroll
            for (int t = 0; t < 4; t++) bc[t] = bn[t];
        }
        __syncthreads();           // all row reads done before next overwrite
    }

    // epilogue: scale by 1/||x_win||, relu, store
    int h = h0 + dh;
    if (h < HO) {
        const float* ivrow = g_inv + (n * HO + h) * WO;
        #pragma unroll
        for (int mt = 0; mt < 4; mt++) {
            int w0 = whalf * 64 + mt * 16 + gid;
            float iv0 = (w0 < WO)     ? ivrow[w0]     : 0.f;
            float iv8 = (w0 + 8 < WO) ? ivrow[w0 + 8] : 0.f;
            #pragma unroll
            for (int t = 0; t < 4; t++) {
                int o = ns * 32 + t * 8 + tig * 2;
                float* ob = out + ((n * OO + o) * HO + h) * WO;
                if (w0 < WO) {
                    float v0 = acc[mt][t][0] * iv0;
                    float v1 = acc[mt][t][1] * iv0;
                    ob[w0]           = v0 > 0.f ? v0 : 0.f;
                    ob[HO*WO + w0]   = v1 > 0.f ? v1 : 0.f;
                }
                if (w0 + 8 < WO) {
                    float v2 = acc[mt][t][2] * iv8;
                    float v3 = acc[mt][t][3] * iv8;
                    ob[w0 + 8]         = v2 > 0.f ? v2 : 0.f;
                    ob[HO*WO + w0 + 8] = v3 > 0.f ? v3 : 0.f;
                }
            }
        }
    }
}

extern "C" void kernel_launch(void* const* d_in, const int* in_sizes, int n_in,
                              void* d_out, int out_size) {
    const float* x = (const float*)d_in[0];   // (16,64,128,128)
    const float* y = (const float*)d_in[1];   // (64,64,16,16)
    float* out = (float*)d_out;               // (16,64,113,113)

    k_norm_y<<<OO, 256>>>(y);
    k_bfrag<<<CC*KH, 256>>>();
    k_xsq<<<(NN*HH*WW) / 256, 256>>>(x);
    k_boxw<<<NN * HH, WW>>>();
    k_boxh<<<(NN*HO*WO + 255) / 256, 256>>>();

    dim3 grid((HO + TH - 1) / TH, NN);
    k_conv_mma<<<grid, 256>>>(x, out);
}